// round 15
// baseline (speedup 1.0000x reference)
#include <cuda_runtime.h>
#include <cuda_fp16.h>
typedef unsigned long long ull;

#define NT 416
#define Tt 512
#define Hh 50

#define OFF_B  0u
#define B_LO   5376u
#define B_T    10752u
#define OFF_G  21504u
#define G_T    28800u
#define OFF_BI 79104u
#define OFF_WX 80704u
#define OFF_FC 82304u
#define OFF_X  82560u
#define SMEM_BYTES 82816u

#define LDMX4T(r0,r1,r2,r3,a) \
  asm volatile("ldmatrix.sync.aligned.m8n8.x4.trans.shared.b16 {%0,%1,%2,%3}, [%4];" \
    : "=r"(r0),"=r"(r1),"=r"(r2),"=r"(r3) : "r"(a))

__device__ __forceinline__ void mma16816(float* d, const uint4& a,
                                         unsigned b0, unsigned b1) {
    asm volatile("mma.sync.aligned.m16n8k16.row.col.f32.f16.f16.f32 "
        "{%0,%1,%2,%3}, {%4,%5,%6,%7}, {%8,%9}, {%0,%1,%2,%3};"
        : "+f"(d[0]), "+f"(d[1]), "+f"(d[2]), "+f"(d[3])
        : "r"(a.x), "r"(a.y), "r"(a.z), "r"(a.w), "r"(b0), "r"(b1));
}
__device__ __forceinline__ float rcpa(float v) {
    float r; asm("rcp.approx.f32 %0, %1;" : "=f"(r) : "f"(v)); return r;
}
__device__ __forceinline__ float ex2a(float v) {
    float r; asm("ex2.approx.f32 %0, %1;" : "=f"(r) : "f"(v)); return r;
}
#define L2E  1.4426950408889634f
#define L2E2 2.8853901617779268f

__device__ __forceinline__ float cellup(float& c, float gi, float gf,
                                        float gg, float go) {
    float ei = ex2a(-L2E * gi), ef = ex2a(-L2E * gf);
    float eg = ex2a(-L2E2 * gg), eo = ex2a(-L2E * go);
    float rig = rcpa((1.f + ei) * (1.f + eg));
    c = rcpa(1.f + ef) * c + (1.f - eg) * rig;
    float ec = ex2a(-L2E2 * c);
    return (1.f - ec) * rcpa((1.f + eo) * (1.f + ec));
}
__device__ __forceinline__ float valA(int M, int k,
    const float* __restrict__ whh0, const float* __restrict__ wih1,
    const float* __restrict__ whh1) {
    if (k >= 100) return 0.f;
    if (M < 200) return (k < Hh) ? whh0[M * Hh + k] : 0.f;
    int r = M - 200;
    return (k < Hh) ? wih1[r * Hh + k] : whh1[r * Hh + (k - Hh)];
}
__device__ __forceinline__ unsigned packh2(float a, float b) {
    __half2 h = __halves2half2(__float2half_rn(a), __float2half_rn(b));
    return *(unsigned*)&h;
}

__global__ __launch_bounds__(NT, 1)
void lstm2_pipe_kernel(
    const float* __restrict__ x,
    const float* __restrict__ wih0, const float* __restrict__ whh0,
    const float* __restrict__ bih0, const float* __restrict__ bhh0,
    const float* __restrict__ wih1, const float* __restrict__ whh1,
    const float* __restrict__ bih1, const float* __restrict__ bhh1,
    const float* __restrict__ fcw,  const float* __restrict__ fcb,
    float* __restrict__ out)
{
    extern __shared__ char smp[];
    const unsigned sb = (unsigned)__cvta_generic_to_shared(smp);
    const int tid = threadIdx.x, lane = tid & 31, wid = tid >> 5;
    const int b0i = blockIdx.x * 32;

    // ---- init smem ----
    for (unsigned i = tid * 4u; i < 21504u; i += NT * 4u)       // zero h tiles
        *(unsigned*)(smp + OFF_B + i) = 0u;
    for (int i = tid; i < 200; i += NT) {
        *(float*)(smp + OFF_BI + i * 4)       = bih0[i] + bhh0[i];
        *(float*)(smp + OFF_BI + 800 + i * 4) = bih1[i] + bhh1[i];
        *(float*)(smp + OFF_WX + i * 4)       = wih0[i];
        *(float*)(smp + OFF_WX + 800 + i * 4) = 0.f;
    }
    for (int i = tid; i < 6400; i += NT) {       // G layer-1 rows = b0 + wih0*x(0)
        int tau = i / 3200, rem = i - 3200 * tau, r = rem >> 4, b = rem & 15;
        float xv = x[(ull)(b0i + tau * 16 + b) * Tt];
        *(float*)(smp + OFF_G + (unsigned)tau * G_T + r * 72u + b * 4u)
            = (bih0[r] + bhh0[r]) + wih0[r] * xv;
    }
    if (tid < Hh) *(float*)(smp + OFF_FC + tid * 4) = fcw[tid];
    if (tid == Hh) *(float*)(smp + OFF_FC + 200) = fcb[0];
    if (tid < 32) *(float*)(smp + OFF_X + 128 + tid * 4) = x[(ull)(b0i + tid) * Tt + 1];
    __syncthreads();

    // ---- A fragments -> registers (hi/lo), built straight from gmem ----
    const bool hasA = (wid < 12);
    const int ma = hasA ? wid : 0, mb = hasA ? 12 + wid : 24;
    uint4 Aa[4][2], Ab[7][2];
    #pragma unroll
    for (int s = 0; s < 7; ++s) {
        unsigned hv[4], lv[4];
        #pragma unroll
        for (int r = 0; r < 4; ++r) {
            int row = 16 * mb + (lane >> 2) + (r & 1) * 8;
            int kk  = 16 * s + (lane & 3) * 2 + (r >> 1) * 8;
            float v0 = valA(row, kk, whh0, wih1, whh1);
            float v1 = valA(row, kk + 1, whh0, wih1, whh1);
            hv[r] = packh2(v0, v1);
            lv[r] = packh2(v0 - __half2float(__float2half_rn(v0)),
                           v1 - __half2float(__float2half_rn(v1)));
        }
        Ab[s][0] = make_uint4(hv[0], hv[1], hv[2], hv[3]);
        Ab[s][1] = make_uint4(lv[0], lv[1], lv[2], lv[3]);
    }
    #pragma unroll
    for (int s = 0; s < 4; ++s) {
        unsigned hv[4], lv[4];
        #pragma unroll
        for (int r = 0; r < 4; ++r) {
            int row = 16 * ma + (lane >> 2) + (r & 1) * 8;
            int kk  = 16 * s + (lane & 3) * 2 + (r >> 1) * 8;
            float v0 = valA(row, kk, whh0, wih1, whh1);
            float v1 = valA(row, kk + 1, whh0, wih1, whh1);
            hv[r] = packh2(v0, v1);
            lv[r] = packh2(v0 - __half2float(__float2half_rn(v0)),
                           v1 - __half2float(__float2half_rn(v1)));
        }
        Aa[s][0] = make_uint4(hv[0], hv[1], hv[2], hv[3]);
        Aa[s][1] = make_uint4(lv[0], lv[1], lv[2], lv[3]);
    }

    const unsigned ko = (lane & 7) + 8u * ((lane >> 3) & 1), nto = lane >> 4;
    const unsigned gid = lane >> 2, tig = lane & 3;

    auto storeT = [&](char* Gt, int m, float* D, float2 x0, float2 x1) {
        int r0 = 16 * m + (int)gid, r1 = r0 + 8;
        float bi0 = *(const float*)(smp + OFF_BI + r0 * 4);
        float bi1 = *(const float*)(smp + OFF_BI + r1 * 4);
        float w0  = *(const float*)(smp + OFF_WX + r0 * 4);
        float w1  = *(const float*)(smp + OFF_WX + r1 * 4);
        *(float2*)(Gt + r0 * 72u + tig * 8u) =
            make_float2(D[0] + bi0 + w0 * x0.x, D[1] + bi0 + w0 * x0.y);
        *(float2*)(Gt + r1 * 72u + tig * 8u) =
            make_float2(D[2] + bi1 + w1 * x0.x, D[3] + bi1 + w1 * x0.y);
        *(float2*)(Gt + r0 * 72u + 32u + tig * 8u) =
            make_float2(D[4] + bi0 + w0 * x1.x, D[5] + bi0 + w0 * x1.y);
        *(float2*)(Gt + r1 * 72u + 32u + tig * 8u) =
            make_float2(D[6] + bi1 + w1 * x1.x, D[7] + bi1 + w1 * x1.y);
    };

    auto gemm = [&](int tau, int tg) {
        unsigned bB = sb + OFF_B + (unsigned)tau * B_T + ko * 48u + nto * 16u;
        float Da[8], Db[8];
        #pragma unroll
        for (int q = 0; q < 8; ++q) { Da[q] = 0.f; Db[q] = 0.f; }
        #pragma unroll
        for (int s = 0; s < 7; ++s) {
            unsigned h0r, h1r, h2r, h3r, l0r, l1r, l2r, l3r;
            LDMX4T(h0r, h1r, h2r, h3r, bB + (unsigned)s * 768u);
            LDMX4T(l0r, l1r, l2r, l3r, bB + (unsigned)s * 768u + B_LO);
            mma16816(Db,     Ab[s][0], h0r, h1r);
            mma16816(Db,     Ab[s][1], h0r, h1r);
            mma16816(Db,     Ab[s][0], l0r, l1r);
            mma16816(Db + 4, Ab[s][0], h2r, h3r);
            mma16816(Db + 4, Ab[s][1], h2r, h3r);
            mma16816(Db + 4, Ab[s][0], l2r, l3r);
            if (s < 4 && hasA) {
                mma16816(Da,     Aa[s][0], h0r, h1r);
                mma16816(Da,     Aa[s][1], h0r, h1r);
                mma16816(Da,     Aa[s][0], l0r, l1r);
                mma16816(Da + 4, Aa[s][0], h2r, h3r);
                mma16816(Da + 4, Aa[s][1], h2r, h3r);
                mma16816(Da + 4, Aa[s][0], l2r, l3r);
            }
        }
        char* Gt = smp + OFF_G + (unsigned)tau * G_T;
        const char* xb = smp + OFF_X + (unsigned)((tg + 1) & 1) * 128u
                       + (unsigned)tau * 64u;
        float2 x0 = *(const float2*)(xb + tig * 8u);
        float2 x1 = *(const float2*)(xb + 32u + tig * 8u);
        storeT(Gt, mb, Db, x0, x1);
        if (hasA) storeT(Gt, ma, Da, x0, x1);
    };

    float c0s[2][2] = {{0.f,0.f},{0.f,0.f}}, c1s[2][2] = {{0.f,0.f},{0.f,0.f}};

    auto docell = [&](int tau, float (&cs)[2][2], bool dol1, bool dol2) {
        char* Gt = smp + OFF_G + (unsigned)tau * G_T;
        char* Bt = smp + OFF_B + (unsigned)tau * B_T;
        #pragma unroll
        for (int i = 0; i < 2; ++i) {
            int idx = tid + NT * i;
            if (idx < 800) {
                int layer = (idx >= 400) ? 1 : 0;
                int q = idx - 400 * layer;
                int u = 2 * (q >> 4), b = q & 15;
                if (layer ? dol2 : dol1) {
                    #pragma unroll
                    for (int j = 0; j < 2; ++j) {
                        int r = 200 * layer + u + j;
                        float gi = *(const float*)(Gt + r * 72u + b * 4u);
                        float gf = *(const float*)(Gt + (r + 50) * 72u + b * 4u);
                        float gg = *(const float*)(Gt + (r + 100) * 72u + b * 4u);
                        float go = *(const float*)(Gt + (r + 150) * 72u + b * 4u);
                        float h = cellup(cs[i][j], gi, gf, gg, go);
                        int kk = layer * 50 + u + j;
                        __half hh = __float2half_rn(h);
                        *(__half*)(Bt + kk * 48u + b * 2u) = hh;
                        *(__half*)(Bt + B_LO + kk * 48u + b * 2u) =
                            __float2half_rn(h - __half2float(hh));
                    }
                }
            }
        }
    };

    // pre-loop: cell1(0) for both tiles from G-init gates
    docell(0, c0s, true, false);
    docell(1, c1s, true, false);
    __syncthreads();

    // ---- phase loop: phase p = GEMM(tile p&1, p>>1)  ||  cells(other tile) ----
    for (int p = 0; p <= 2 * Tt; ++p) {
        int tg = p >> 1, taug = p & 1;
        float xr = 0.f;
        bool dox = (taug == 1) && (tid < 32) && (tg + 2 < Tt);
        if (dox) xr = x[(ull)(b0i + tid) * Tt + tg + 2];
        bool dog = (p < 2 * Tt);
        int tc = (p - 1) >> 1;
        bool doc = (p >= 1);
        bool dol1 = (tc + 1 < Tt);
        if (wid & 1) {
            if (doc) { if (taug) docell(0, c0s, dol1, true);
                       else      docell(1, c1s, dol1, true); }
            if (dog) gemm(taug, tg);
        } else {
            if (dog) gemm(taug, tg);
            if (doc) { if (taug) docell(0, c0s, dol1, true);
                       else      docell(1, c1s, dol1, true); }
        }
        if (dox) *(float*)(smp + OFF_X + (unsigned)(tg & 1) * 128u + tid * 4u) = xr;
        __syncthreads();
    }

    // ---- final FC on h1(T-1) (hi+lo f16 from B buffer) ----
    if (tid < 32) {
        int tau = tid >> 4, b = tid & 15;
        char* Bt = smp + OFF_B + (unsigned)tau * B_T;
        float acc = *(const float*)(smp + OFF_FC + 200);
        #pragma unroll
        for (int u = 0; u < Hh; ++u) {
            unsigned o = (unsigned)(50 + u) * 48u + (unsigned)b * 2u;
            float h = __half2float(*(const __half*)(Bt + o))
                    + __half2float(*(const __half*)(Bt + B_LO + o));
            acc += h * *(const float*)(smp + OFF_FC + u * 4);
        }
        out[b0i + tid] = acc;
    }
}

extern "C" void kernel_launch(void* const* d_in, const int* in_sizes, int n_in,
                              void* d_out, int out_size)
{
    const float* x    = (const float*)d_in[0];
    const float* wih0 = (const float*)d_in[1];
    const float* whh0 = (const float*)d_in[2];
    const float* bih0 = (const float*)d_in[3];
    const float* bhh0 = (const float*)d_in[4];
    const float* wih1 = (const float*)d_in[5];
    const float* whh1 = (const float*)d_in[6];
    const float* bih1 = (const float*)d_in[7];
    const float* bhh1 = (const float*)d_in[8];
    const float* fcw  = (const float*)d_in[9];
    const float* fcb  = (const float*)d_in[10];
    float* out = (float*)d_out;

    const int B = in_sizes[0] / Tt;   // 4096
    const int grid = B / 32;          // 128

    cudaFuncSetAttribute(lstm2_pipe_kernel,
                         cudaFuncAttributeMaxDynamicSharedMemorySize, SMEM_BYTES);

    lstm2_pipe_kernel<<<grid, NT, SMEM_BYTES>>>(
        x, wih0, whh0, bih0, bhh0, wih1, whh1, bih1, bhh1, fcw, fcb, out);
}